// round 14
// baseline (speedup 1.0000x reference)
#include <cuda_runtime.h>
#include <cuda_fp16.h>
#include <cstdint>

#define TT 2048
#define BB 256
#define CH 64
#define WU 32
#define NCHUNK (TT / CH)   // 32

#define LOG2E 1.4426950408889634f
#define LN2   0.6931471805599453f

// Warp-uniform max of positive floats via integer redux (f32 redux not on sm_103).
__device__ __forceinline__ float warp_max_pos(float v) {
    unsigned r;
    asm volatile("redux.sync.max.u32 %0, %1, 0xffffffff;"
                 : "=r"(r) : "r"(__float_as_uint(v)));
    return __uint_as_float(r);
}

__device__ __forceinline__ float ex2(float x) {
    float y; asm("ex2.approx.f32 %0, %1;" : "=f"(y) : "f"(x)); return y;
}
__device__ __forceinline__ float lg2(float x) {
    float y; asm("lg2.approx.f32 %0, %1;" : "=f"(y) : "f"(x)); return y;
}

// -floor(log2(m)) for positive normal m, via exponent field (ALU only, exact).
__device__ __forceinline__ float neg_exp_floor(float m) {
    int e = (int)(__float_as_uint(m) >> 23) - 127;
    return (float)(-e);
}

// sign = 1 - 2*((popc(s&mask) ^ b) & 1)
__device__ __forceinline__ float sg(int s, int mask, int b) {
    return 1.0f - 2.0f * (float)((__popc(s & mask) ^ b) & 1);
}

// ---------------------------------------------------------------------------
// One block per (batch, 64-step chunk), 2 warps.
// Warp0: alpha recursion (uniform seed WU steps early; exact delta for c=0).
// Warp1: beta recursion (uniform seed WU steps late; exact for last chunk).
// 3-MUFU gamma step: A1,A4,tY=ex2(-2y) then A3=A1*tY, A2=A4*tY (exact).
// Power-of-2 zero-lag normalization folded into each group's first step.
// Raw (clamped) carries stored; LLR invariant to per-t row scale.
// fp16 smem transposed [state][t] (stride CH+1); lane-per-t LLR with
// sign-group partial sums and 2-exp (P,Q polynomial) combine.
// ---------------------------------------------------------------------------
__global__ __launch_bounds__(64, 1)
void bcjr_kernel(const float* __restrict__ llr_ch, const float* __restrict__ llr_a,
                 float* __restrict__ out) {
    __shared__ __half2 sA[32][CH + 1];
    __shared__ __half2 sB[32][CH + 1];

    const int c = blockIdx.x & (NCHUNK - 1);
    const int b = blockIdx.x >> 5;           // NCHUNK = 32
    const int tb = c * CH;
    const int w = threadIdx.x >> 5;
    const int L = threadIdx.x & 31;

    const float*  ch  = llr_ch + (size_t)b * (2 * TT);
    const float4* ch4 = (const float4*)ch;
    const float*  la  = llr_a + (size_t)b * TT;
    const float2* la2 = (const float2*)la;

    const __half2 HCLAMP = __float2half2_rn(60000.0f);

    if (w == 0) {
        // ---- alpha: warmup + chunk ----
        const int bit = L >> 4;
        const int p0 = (2 * L) & 31, p1 = p0 + 1;
        const float h0 = 0.5f * LOG2E * sg(2 * p0, 57, bit);
        const float h1 = 0.5f * LOG2E * sg(2 * p0, 27, bit);
        const float hb = 0.5f * LOG2E * (1.0f - 2.0f * (float)bit);
        const float th0 = -2.0f * h0;
        const float th1 = -2.0f * h1;

        float a0, a1;
        int gs;
        if (c == 0) { a0 = (L == 0) ? 1.0f : 0.0f; a1 = 0.0f; gs = 0; }
        else        { a0 = 1.0f / 64.0f; a1 = 1.0f / 64.0f;   gs = -WU; }

        for (int g = gs; g < CH; g += 4) {
            float mlr = neg_exp_floor(warp_max_pos(a0 + a1));   // folded into step 0
            const bool st = (g >= 0);

            const int tv = (tb + g) >> 1;
            float4 cA = __ldg(ch4 + tv);
            float4 cB = __ldg(ch4 + tv + 1);
            float2 dA = __ldg(la2 + tv);
            float2 dB = __ldg(la2 + tv + 1);
            float l0v[4] = {cA.x, cA.z, cB.x, cB.z};
            float l1v[4] = {cA.y, cA.w, cB.y, cB.w};
            float lav[4] = {dA.x, dA.y, dB.x, dB.y};

#pragma unroll
            for (int k = 0; k < 4; k++) {
                if (st)
                    sA[L][g + k] = __hmin2(__floats2half2_rn(a0, a1), HCLAMP);

                float z = (k == 0) ? fmaf(hb, lav[k], mlr) : hb * lav[k];
                float a1arg = fmaf(h0, l0v[k], fmaf(h1, l1v[k], z));  // z + x + y
                float a4arg = fmaf(th0, l0v[k], a1arg);               // z - x + y
                float tYarg = th1 * l1v[k];                           // -2y
                float A1 = ex2(a1arg);   // gamma(2p0,   bit)
                float A4 = ex2(a4arg);   // gamma(2p1+1, bit)
                float tY = ex2(tYarg);
                float A3 = A1 * tY;      // gamma(2p1,   bit) = ex2(z + x - y)
                float A2 = A4 * tY;      // gamma(2p0+1, bit) = ex2(z - x - y)

                float pa0 = __shfl_sync(0xffffffffu, a0, p0);
                float pa1 = __shfl_sync(0xffffffffu, a1, p0);
                float qa0 = __shfl_sync(0xffffffffu, a0, p1);
                float qa1 = __shfl_sync(0xffffffffu, a1, p1);

                a0 = fmaf(A2, pa1, A1 * pa0);
                a1 = fmaf(A4, qa1, A3 * qa0);
            }
        }
    } else {
        // ---- beta: warmup + chunk (stride-32 layout: lane L = beta[L], beta[L+32]) ----
        const float x0L = 0.5f * LOG2E * sg(L, 57, 0);
        const float x1L = 0.5f * LOG2E * sg(L, 27, 0);
        const float xbL = 0.5f * LOG2E;
        const float mx0L = -x0L;
        const int srcA = L >> 1;
        const int srcB = 16 + (L >> 1);

        float b0 = 1.0f / 64.0f, b1 = 1.0f / 64.0f;
        const int ge = (c == NCHUNK - 1) ? CH : CH + WU;

        for (int g = ge - 4; g >= 0; g -= 4) {
            float lr = neg_exp_floor(warp_max_pos(b0 + b1));   // folded into first step
            const bool st = (g < CH);

            const int tv = (tb + g) >> 1;
            float4 cA = __ldg(ch4 + tv);
            float4 cB = __ldg(ch4 + tv + 1);
            float2 dA = __ldg(la2 + tv);
            float2 dB = __ldg(la2 + tv + 1);
            float l0v[4] = {cA.x, cA.z, cB.x, cB.z};
            float l1v[4] = {cA.y, cA.w, cB.y, cB.w};
            float lav[4] = {dA.x, dA.y, dB.x, dB.y};

#pragma unroll
            for (int kk = 0; kk < 4; kk++) {
                int k = 3 - kk;
                if (st)
                    sB[L][g + k] = __hmin2(__floats2half2_rn(b0, b1), HCLAMP);

                float bb2 = fmaf(x1L, l1v[k], xbL * lav[k]);          // b2
                float smarg = fmaf(x0L, l0v[k], bb2);                 // a + b2
                float c10arg = fmaf(mx0L, l0v[k], bb2);               // b2 - a
                float tBarg = -(bb2 + bb2);                           // -2*b2
                if (kk == 0) { smarg += lr; c10arg += lr; }
                float Z   = ex2(smarg);    // gamma(L,    0)  [* 2^lr on first step]
                float c10 = ex2(c10arg);   // gamma(L+32, 0)  [* 2^lr]
                float tB  = ex2(tBarg);
                float iZ  = c10 * tB;      // gamma(L,    1)  = ex2(-a-b2) [* 2^lr]
                float c11 = Z * tB;        // gamma(L+32, 1)  = ex2( a-b2) [* 2^lr]

                float s0 = __shfl_sync(0xffffffffu, b0, srcA);
                float s1 = __shfl_sync(0xffffffffu, b1, srcA);
                float t0s = __shfl_sync(0xffffffffu, b0, srcB);
                float t1s = __shfl_sync(0xffffffffu, b1, srcB);

                b0 = fmaf(iZ, s1, Z * s0);
                b1 = fmaf(c11, t1s, c10 * t0s);
            }
        }
    }

    __syncthreads();

    // ---- LLR: lane-per-t, sign-group partial sums; 2-exp polynomial combine ----
    {
        int tl = w * 32 + L;
        int t = tb + tl;
        float2 l01 = __ldg((const float2*)ch + t);
        float l0 = l01.x, l1 = l01.y;
        float laa = __ldg(la + t);

        float sp = 0.5f * LOG2E * (l0 + l1);
        float dm = 0.5f * LOG2E * (l0 - l1);
        float P = ex2(sp);
        float Q = ex2(dm);

        float T0[4] = {0, 0, 0, 0};   // sum bb.x * a.x   per sign-group
        float T1[4] = {0, 0, 0, 0};   // sum bb.x * a.y
        float U0[4] = {0, 0, 0, 0};   // sum bb.y * a.x
        float U1[4] = {0, 0, 0, 0};   // sum bb.y * a.y
#pragma unroll
        for (int s = 0; s < 32; s++) {
            const int par0 = (__popc(s & 28)) & 1;   // sign of l0 term for state 2s
            const int par1 = (__popc(s & 13)) & 1;   // sign of l1 term for state 2s
            const int gI = par0 * 2 + par1;

            float2 a  = __half22float2(sA[s][tl]);
            float2 bb = __half22float2(sB[s][tl]);
            T0[gI] = fmaf(bb.x, a.x, T0[gI]);
            T1[gI] = fmaf(bb.x, a.y, T1[gI]);
            U0[gI] = fmaf(bb.y, a.x, U0[gI]);
            U1[gI] = fmaf(bb.y, a.y, U1[gI]);
        }
        // S0 = P*A + iP*B + Q*C + iQ*D  ->  S0*PQ = A*P2Q + B*Q + C*PQ2 + D*P
        float A  = T0[0] + T1[3], B  = T1[0] + T0[3];
        float C  = T0[1] + T1[2], D  = T1[1] + T0[2];
        float A2 = U1[0] + U0[3], B2 = U0[0] + U1[3];
        float C2 = U1[1] + U0[2], D2 = U0[1] + U1[2];

        float PQ  = P * Q;
        float P2Q = PQ * P;
        float PQ2 = PQ * Q;
        float S0 = fmaf(A,  P2Q, fmaf(C,  PQ2, fmaf(D,  P, B  * Q)));
        float S1 = fmaf(A2, P2Q, fmaf(C2, PQ2, fmaf(D2, P, B2 * Q)));

        out[(size_t)b * TT + t] = fmaf(LN2, lg2(S0) - lg2(S1), laa);
    }
}

extern "C" void kernel_launch(void* const* d_in, const int* in_sizes, int n_in,
                              void* d_out, int out_size) {
    const float* llr_ch = (const float*)d_in[0];   // [256, 4096]
    const float* llr_a  = (const float*)d_in[1];   // [256, 2048]
    float* out = (float*)d_out;                    // [256, 2048]

    bcjr_kernel<<<BB * NCHUNK, 64>>>(llr_ch, llr_a, out);
}

// round 15
// speedup vs baseline: 1.6023x; 1.6023x over previous
#include <cuda_runtime.h>
#include <cuda_fp16.h>
#include <cstdint>

#define TT 2048
#define BB 256
#define CH 64
#define WU 32
#define NCHUNK (TT / CH)   // 32
#define RSTR 68            // smem row stride in words (half2 units); 68/4=17 odd -> STS.128 conflict-free

#define LOG2E 1.4426950408889634f
#define LN2   0.6931471805599453f

// Warp-uniform max of positive floats via integer redux (f32 redux not on sm_103).
__device__ __forceinline__ float warp_max_pos(float v) {
    unsigned r;
    asm volatile("redux.sync.max.u32 %0, %1, 0xffffffff;"
                 : "=r"(r) : "r"(__float_as_uint(v)));
    return __uint_as_float(r);
}

__device__ __forceinline__ float ex2(float x) {
    float y; asm("ex2.approx.f32 %0, %1;" : "=f"(y) : "f"(x)); return y;
}
__device__ __forceinline__ float lg2(float x) {
    float y; asm("lg2.approx.f32 %0, %1;" : "=f"(y) : "f"(x)); return y;
}

// sign = 1 - 2*((popc(s&mask) ^ b) & 1)
__device__ __forceinline__ float sg(int s, int mask, int b) {
    return 1.0f - 2.0f * (float)((__popc(s & mask) ^ b) & 1);
}

// pack two floats to clamped half2 bits
__device__ __forceinline__ unsigned pack16(float x, float y) {
    __half2 h = __hmin2(__floats2half2_rn(x, y), __float2half2_rn(60000.0f));
    return *reinterpret_cast<unsigned*>(&h);
}
__device__ __forceinline__ float2 unpack16(unsigned u) {
    __half2 h = *reinterpret_cast<__half2*>(&u);
    return __half22float2(h);
}

// ---------------------------------------------------------------------------
// One block per (batch, 64-step chunk), 2 warps.
// Warp0: alpha recursion (uniform seed WU steps early; exact delta for c=0).
// Warp1: beta recursion (uniform seed WU steps late; exact for last chunk).
// Warmup and main loops split (no per-step store predicate); carries stored
// raw per step via one STS.128 per 4-step group. Power normalization folded
// into each group's first step (zero lag), as validated in R13.
// smem [state-pair][t] rows of RSTR words; lane-per-t LLR, sign-group partials.
// ---------------------------------------------------------------------------
__global__ __launch_bounds__(64, 1)
void bcjr_kernel(const float* __restrict__ llr_ch, const float* __restrict__ llr_a,
                 float* __restrict__ out) {
    __shared__ __align__(16) unsigned sA[32][RSTR];
    __shared__ __align__(16) unsigned sB[32][RSTR];

    const int c = blockIdx.x & (NCHUNK - 1);
    const int b = blockIdx.x >> 5;           // NCHUNK = 32
    const int tb = c * CH;
    const int w = threadIdx.x >> 5;
    const int L = threadIdx.x & 31;

    const float*  ch  = llr_ch + (size_t)b * (2 * TT);
    const float4* ch4 = (const float4*)ch;
    const float*  la  = llr_a + (size_t)b * TT;
    const float2* la2 = (const float2*)la;

    if (w == 0) {
        // ---- alpha ----
        const int bit = L >> 4;
        const int p0 = (2 * L) & 31, p1 = p0 + 1;
        const float h0 = 0.5f * LOG2E * sg(2 * p0, 57, bit);
        const float h1 = 0.5f * LOG2E * sg(2 * p0, 27, bit);
        const float hb = 0.5f * LOG2E * (1.0f - 2.0f * (float)bit);

        float a0, a1;
        if (c == 0) { a0 = (L == 0) ? 1.0f : 0.0f; a1 = 0.0f; }
        else        { a0 = 1.0f / 64.0f; a1 = 1.0f / 64.0f; }

        // ---- warmup (no stores) ----
        if (c != 0) {
            for (int g = -WU; g < 0; g += 4) {
                float mlr = -lg2(warp_max_pos(a0 + a1));
                const int tv = (tb + g) >> 1;
                float4 cA = __ldg(ch4 + tv);
                float4 cB = __ldg(ch4 + tv + 1);
                float2 dA = __ldg(la2 + tv);
                float2 dB = __ldg(la2 + tv + 1);
                float l0v[4] = {cA.x, cA.z, cB.x, cB.z};
                float l1v[4] = {cA.y, cA.w, cB.y, cB.w};
                float lav[4] = {dA.x, dA.y, dB.x, dB.y};
#pragma unroll
                for (int k = 0; k < 4; k++) {
                    float x = h0 * l0v[k];
                    float y = h1 * l1v[k];
                    float z = (k == 0) ? fmaf(hb, lav[k], mlr) : hb * lav[k];
                    float spy = x + y, dmy = x - y;
                    float A1 = ex2(z + spy);
                    float A2 = ex2(z - spy);
                    float A3 = ex2(z + dmy);
                    float A4 = ex2(z - dmy);
                    float pa0 = __shfl_sync(0xffffffffu, a0, p0);
                    float pa1 = __shfl_sync(0xffffffffu, a1, p0);
                    float qa0 = __shfl_sync(0xffffffffu, a0, p1);
                    float qa1 = __shfl_sync(0xffffffffu, a1, p1);
                    a0 = fmaf(A2, pa1, A1 * pa0);
                    a1 = fmaf(A4, qa1, A3 * qa0);
                }
            }
        }

        // ---- main (stores, no predicate) ----
        for (int g = 0; g < CH; g += 4) {
            float mlr = -lg2(warp_max_pos(a0 + a1));
            const int tv = (tb + g) >> 1;
            float4 cA = __ldg(ch4 + tv);
            float4 cB = __ldg(ch4 + tv + 1);
            float2 dA = __ldg(la2 + tv);
            float2 dB = __ldg(la2 + tv + 1);
            float l0v[4] = {cA.x, cA.z, cB.x, cB.z};
            float l1v[4] = {cA.y, cA.w, cB.y, cB.w};
            float lav[4] = {dA.x, dA.y, dB.x, dB.y};
            unsigned u[4];
#pragma unroll
            for (int k = 0; k < 4; k++) {
                u[k] = pack16(a0, a1);

                float x = h0 * l0v[k];
                float y = h1 * l1v[k];
                float z = (k == 0) ? fmaf(hb, lav[k], mlr) : hb * lav[k];
                float spy = x + y, dmy = x - y;
                float A1 = ex2(z + spy);
                float A2 = ex2(z - spy);
                float A3 = ex2(z + dmy);
                float A4 = ex2(z - dmy);
                float pa0 = __shfl_sync(0xffffffffu, a0, p0);
                float pa1 = __shfl_sync(0xffffffffu, a1, p0);
                float qa0 = __shfl_sync(0xffffffffu, a0, p1);
                float qa1 = __shfl_sync(0xffffffffu, a1, p1);
                a0 = fmaf(A2, pa1, A1 * pa0);
                a1 = fmaf(A4, qa1, A3 * qa0);
            }
            *reinterpret_cast<uint4*>(&sA[L][g]) = make_uint4(u[0], u[1], u[2], u[3]);
        }
    } else {
        // ---- beta (stride-32 layout: lane L = beta[L], beta[L+32]) ----
        const float x0L = 0.5f * LOG2E * sg(L, 57, 0);
        const float x1L = 0.5f * LOG2E * sg(L, 27, 0);
        const float xbL = 0.5f * LOG2E;
        const int srcA = L >> 1;
        const int srcB = 16 + (L >> 1);

        float b0 = 1.0f / 64.0f, b1 = 1.0f / 64.0f;

        // ---- warmup (no stores) ----
        if (c != NCHUNK - 1) {
            for (int g = CH + WU - 4; g >= CH; g -= 4) {
                float lr = -lg2(warp_max_pos(b0 + b1));
                const int tv = (tb + g) >> 1;
                float4 cA = __ldg(ch4 + tv);
                float4 cB = __ldg(ch4 + tv + 1);
                float2 dA = __ldg(la2 + tv);
                float2 dB = __ldg(la2 + tv + 1);
                float l0v[4] = {cA.x, cA.z, cB.x, cB.z};
                float l1v[4] = {cA.y, cA.w, cB.y, cB.w};
                float lav[4] = {dA.x, dA.y, dB.x, dB.y};
#pragma unroll
                for (int kk = 0; kk < 4; kk++) {
                    int k = 3 - kk;
                    float a = x0L * l0v[k];
                    float b2 = fmaf(x1L, l1v[k], xbL * lav[k]);
                    float sm = a + b2, df = a - b2;
                    float zp, zm, dp, dn;
                    if (kk == 0) { zp = sm + lr; zm = lr - sm; dp = lr + df; dn = lr - df; }
                    else         { zp = sm;      zm = -sm;      dp = df;      dn = -df;     }
                    float Z   = ex2(zp);
                    float iZ  = ex2(zm);
                    float c10 = ex2(dn);
                    float c11 = ex2(dp);
                    float s0 = __shfl_sync(0xffffffffu, b0, srcA);
                    float s1 = __shfl_sync(0xffffffffu, b1, srcA);
                    float t0s = __shfl_sync(0xffffffffu, b0, srcB);
                    float t1s = __shfl_sync(0xffffffffu, b1, srcB);
                    b0 = fmaf(iZ, s1, Z * s0);
                    b1 = fmaf(c11, t1s, c10 * t0s);
                }
            }
        }

        // ---- main (stores, no predicate) ----
        for (int g = CH - 4; g >= 0; g -= 4) {
            float lr = -lg2(warp_max_pos(b0 + b1));
            const int tv = (tb + g) >> 1;
            float4 cA = __ldg(ch4 + tv);
            float4 cB = __ldg(ch4 + tv + 1);
            float2 dA = __ldg(la2 + tv);
            float2 dB = __ldg(la2 + tv + 1);
            float l0v[4] = {cA.x, cA.z, cB.x, cB.z};
            float l1v[4] = {cA.y, cA.w, cB.y, cB.w};
            float lav[4] = {dA.x, dA.y, dB.x, dB.y};
            unsigned u[4];
#pragma unroll
            for (int kk = 0; kk < 4; kk++) {
                int k = 3 - kk;
                u[k] = pack16(b0, b1);   // carry = beta_{t+1} at slot t = g + k

                float a = x0L * l0v[k];
                float b2 = fmaf(x1L, l1v[k], xbL * lav[k]);
                float sm = a + b2, df = a - b2;
                float zp, zm, dp, dn;
                if (kk == 0) { zp = sm + lr; zm = lr - sm; dp = lr + df; dn = lr - df; }
                else         { zp = sm;      zm = -sm;      dp = df;      dn = -df;     }
                float Z   = ex2(zp);
                float iZ  = ex2(zm);
                float c10 = ex2(dn);
                float c11 = ex2(dp);
                float s0 = __shfl_sync(0xffffffffu, b0, srcA);
                float s1 = __shfl_sync(0xffffffffu, b1, srcA);
                float t0s = __shfl_sync(0xffffffffu, b0, srcB);
                float t1s = __shfl_sync(0xffffffffu, b1, srcB);
                b0 = fmaf(iZ, s1, Z * s0);
                b1 = fmaf(c11, t1s, c10 * t0s);
            }
            *reinterpret_cast<uint4*>(&sB[L][g]) = make_uint4(u[0], u[1], u[2], u[3]);
        }
    }

    __syncthreads();

    // ---- LLR: lane-per-t, sign-group partial sums (R13 form) ----
    {
        int tl = w * 32 + L;
        int t = tb + tl;
        float2 l01 = __ldg((const float2*)ch + t);
        float l0 = l01.x, l1 = l01.y;
        float laa = __ldg(la + t);

        float sp = 0.5f * LOG2E * (l0 + l1);
        float dm = 0.5f * LOG2E * (l0 - l1);
        float P   = ex2(sp);
        float iPv = ex2(-sp);
        float Q   = ex2(dm);
        float iQv = ex2(-dm);

        float T0[4] = {0, 0, 0, 0};
        float T1[4] = {0, 0, 0, 0};
        float U0[4] = {0, 0, 0, 0};
        float U1[4] = {0, 0, 0, 0};
#pragma unroll
        for (int s = 0; s < 32; s++) {
            const int par0 = (__popc(s & 28)) & 1;
            const int par1 = (__popc(s & 13)) & 1;
            const int gI = par0 * 2 + par1;

            float2 a  = unpack16(sA[s][tl]);
            float2 bb = unpack16(sB[s][tl]);
            T0[gI] = fmaf(bb.x, a.x, T0[gI]);
            T1[gI] = fmaf(bb.x, a.y, T1[gI]);
            U0[gI] = fmaf(bb.y, a.x, U0[gI]);
            U1[gI] = fmaf(bb.y, a.y, U1[gI]);
        }
        // group: 0 -> X=P, 1 -> X=Q, 2 -> X=iQ, 3 -> X=iP
        float S0 = P   * (T0[0] + T1[3]) + iPv * (T1[0] + T0[3])
                 + Q   * (T0[1] + T1[2]) + iQv * (T1[1] + T0[2]);
        float S1 = P   * (U1[0] + U0[3]) + iPv * (U0[0] + U1[3])
                 + Q   * (U1[1] + U0[2]) + iQv * (U0[1] + U1[2]);

        out[(size_t)b * TT + t] = fmaf(LN2, lg2(S0) - lg2(S1), laa);
    }
}

extern "C" void kernel_launch(void* const* d_in, const int* in_sizes, int n_in,
                              void* d_out, int out_size) {
    const float* llr_ch = (const float*)d_in[0];   // [256, 4096]
    const float* llr_a  = (const float*)d_in[1];   // [256, 2048]
    float* out = (float*)d_out;                    // [256, 2048]

    bcjr_kernel<<<BB * NCHUNK, 64>>>(llr_ch, llr_a, out);
}

// round 16
// speedup vs baseline: 1.6167x; 1.0090x over previous
#include <cuda_runtime.h>
#include <cuda_fp16.h>
#include <cstdint>

#define TT 2048
#define BB 256
#define CH 64
#define WU 32
#define NCHUNK (TT / CH)   // 32
#define RSTR 68            // smem row stride in words; 68/4=17 odd -> STS.128 conflict-free

#define LOG2E 1.4426950408889634f
#define LN2   0.6931471805599453f

// Warp-uniform max of positive floats via integer redux (f32 redux not on sm_103).
__device__ __forceinline__ float warp_max_pos(float v) {
    unsigned r;
    asm volatile("redux.sync.max.u32 %0, %1, 0xffffffff;"
                 : "=r"(r) : "r"(__float_as_uint(v)));
    return __uint_as_float(r);
}

__device__ __forceinline__ float ex2(float x) {
    float y; asm("ex2.approx.f32 %0, %1;" : "=f"(y) : "f"(x)); return y;
}
__device__ __forceinline__ float lg2(float x) {
    float y; asm("lg2.approx.f32 %0, %1;" : "=f"(y) : "f"(x)); return y;
}

// sign = 1 - 2*((popc(s&mask) ^ b) & 1)
__device__ __forceinline__ float sg(int s, int mask, int b) {
    return 1.0f - 2.0f * (float)((__popc(s & mask) ^ b) & 1);
}

// pack two floats to clamped half2 bits
__device__ __forceinline__ unsigned pack16(float x, float y) {
    __half2 h = __hmin2(__floats2half2_rn(x, y), __float2half2_rn(60000.0f));
    return *reinterpret_cast<unsigned*>(&h);
}
__device__ __forceinline__ float2 unpack16(unsigned u) {
    __half2 h = *reinterpret_cast<__half2*>(&u);
    return __half22float2(h);
}

// ---------------------------------------------------------------------------
// One block per (batch, 64-step chunk), 2 warps.
// Warp0: alpha recursion (uniform seed WU steps early; exact delta for c=0).
// Warp1: beta recursion (uniform seed WU steps late; exact for last chunk).
// Split warmup/main loops; one STS.128 per 4-step group; power-of-... (lg2)
// zero-lag normalization folded into each group's first step.
// Alpha ex2 args via the 2z identity (7 ops, args stay MUFU-independent).
// smem [state-pair][t] rows of RSTR words; lane-per-t LLR, sign-group partials.
// ---------------------------------------------------------------------------
__global__ __launch_bounds__(64, 1)
void bcjr_kernel(const float* __restrict__ llr_ch, const float* __restrict__ llr_a,
                 float* __restrict__ out) {
    __shared__ __align__(16) unsigned sA[32][RSTR];
    __shared__ __align__(16) unsigned sB[32][RSTR];

    const int c = blockIdx.x & (NCHUNK - 1);
    const int b = blockIdx.x >> 5;           // NCHUNK = 32
    const int tb = c * CH;
    const int w = threadIdx.x >> 5;
    const int L = threadIdx.x & 31;

    const float*  ch  = llr_ch + (size_t)b * (2 * TT);
    const float4* ch4 = (const float4*)ch;
    const float*  la  = llr_a + (size_t)b * TT;
    const float4* la4 = (const float4*)la;

    if (w == 0) {
        // ---- alpha ----
        const int bit = L >> 4;
        const int p0 = (2 * L) & 31, p1 = p0 + 1;
        const float h0 = 0.5f * LOG2E * sg(2 * p0, 57, bit);
        const float h1 = 0.5f * LOG2E * sg(2 * p0, 27, bit);
        const float hb = 0.5f * LOG2E * (1.0f - 2.0f * (float)bit);
        const float th1 = -2.0f * h1;

        float a0, a1;
        if (c == 0) { a0 = (L == 0) ? 1.0f : 0.0f; a1 = 0.0f; }
        else        { a0 = 1.0f / 64.0f; a1 = 1.0f / 64.0f; }

        // ---- warmup (no stores) ----
        if (c != 0) {
#pragma unroll 2
            for (int g = -WU; g < 0; g += 4) {
                float mlr = -lg2(warp_max_pos(a0 + a1));
                const int tv = (tb + g) >> 1;
                float4 cA = __ldg(ch4 + tv);
                float4 cB = __ldg(ch4 + tv + 1);
                float4 dd = __ldg(la4 + ((tb + g) >> 2));
                float l0v[4] = {cA.x, cA.z, cB.x, cB.z};
                float l1v[4] = {cA.y, cA.w, cB.y, cB.w};
                float lav[4] = {dd.x, dd.y, dd.z, dd.w};
#pragma unroll
                for (int k = 0; k < 4; k++) {
                    float z = (k == 0) ? fmaf(hb, lav[k], mlr) : hb * lav[k];
                    float a1arg = fmaf(h0, l0v[k], fmaf(h1, l1v[k], z));  // z+x+y
                    float z2 = z + z;
                    float a2arg = z2 - a1arg;                              // z-x-y
                    float a3arg = fmaf(th1, l1v[k], a1arg);                // z+x-y
                    float a4arg = z2 - a3arg;                              // z-x+y
                    float A1 = ex2(a1arg);
                    float A2 = ex2(a2arg);
                    float A3 = ex2(a3arg);
                    float A4 = ex2(a4arg);
                    float pa0 = __shfl_sync(0xffffffffu, a0, p0);
                    float pa1 = __shfl_sync(0xffffffffu, a1, p0);
                    float qa0 = __shfl_sync(0xffffffffu, a0, p1);
                    float qa1 = __shfl_sync(0xffffffffu, a1, p1);
                    a0 = fmaf(A2, pa1, A1 * pa0);
                    a1 = fmaf(A4, qa1, A3 * qa0);
                }
            }
        }

        // ---- main (stores, no predicate) ----
#pragma unroll 2
        for (int g = 0; g < CH; g += 4) {
            float mlr = -lg2(warp_max_pos(a0 + a1));
            const int tv = (tb + g) >> 1;
            float4 cA = __ldg(ch4 + tv);
            float4 cB = __ldg(ch4 + tv + 1);
            float4 dd = __ldg(la4 + ((tb + g) >> 2));
            float l0v[4] = {cA.x, cA.z, cB.x, cB.z};
            float l1v[4] = {cA.y, cA.w, cB.y, cB.w};
            float lav[4] = {dd.x, dd.y, dd.z, dd.w};
            unsigned u[4];
#pragma unroll
            for (int k = 0; k < 4; k++) {
                u[k] = pack16(a0, a1);

                float z = (k == 0) ? fmaf(hb, lav[k], mlr) : hb * lav[k];
                float a1arg = fmaf(h0, l0v[k], fmaf(h1, l1v[k], z));
                float z2 = z + z;
                float a2arg = z2 - a1arg;
                float a3arg = fmaf(th1, l1v[k], a1arg);
                float a4arg = z2 - a3arg;
                float A1 = ex2(a1arg);
                float A2 = ex2(a2arg);
                float A3 = ex2(a3arg);
                float A4 = ex2(a4arg);
                float pa0 = __shfl_sync(0xffffffffu, a0, p0);
                float pa1 = __shfl_sync(0xffffffffu, a1, p0);
                float qa0 = __shfl_sync(0xffffffffu, a0, p1);
                float qa1 = __shfl_sync(0xffffffffu, a1, p1);
                a0 = fmaf(A2, pa1, A1 * pa0);
                a1 = fmaf(A4, qa1, A3 * qa0);
            }
            *reinterpret_cast<uint4*>(&sA[L][g]) = make_uint4(u[0], u[1], u[2], u[3]);
        }
    } else {
        // ---- beta (stride-32 layout: lane L = beta[L], beta[L+32]) ----
        const float x0L = 0.5f * LOG2E * sg(L, 57, 0);
        const float x1L = 0.5f * LOG2E * sg(L, 27, 0);
        const float xbL = 0.5f * LOG2E;
        const int srcA = L >> 1;
        const int srcB = 16 + (L >> 1);

        float b0 = 1.0f / 64.0f, b1 = 1.0f / 64.0f;

        // ---- warmup (no stores) ----
        if (c != NCHUNK - 1) {
#pragma unroll 2
            for (int g = CH + WU - 4; g >= CH; g -= 4) {
                float lr = -lg2(warp_max_pos(b0 + b1));
                const int tv = (tb + g) >> 1;
                float4 cA = __ldg(ch4 + tv);
                float4 cB = __ldg(ch4 + tv + 1);
                float4 dd = __ldg(la4 + ((tb + g) >> 2));
                float l0v[4] = {cA.x, cA.z, cB.x, cB.z};
                float l1v[4] = {cA.y, cA.w, cB.y, cB.w};
                float lav[4] = {dd.x, dd.y, dd.z, dd.w};
#pragma unroll
                for (int kk = 0; kk < 4; kk++) {
                    int k = 3 - kk;
                    float a = x0L * l0v[k];
                    float b2 = fmaf(x1L, l1v[k], xbL * lav[k]);
                    float sm = a + b2, df = a - b2;
                    float zp, zm, dp, dn;
                    if (kk == 0) { zp = sm + lr; zm = lr - sm; dp = lr + df; dn = lr - df; }
                    else         { zp = sm;      zm = -sm;      dp = df;      dn = -df;     }
                    float Z   = ex2(zp);
                    float iZ  = ex2(zm);
                    float c10 = ex2(dn);
                    float c11 = ex2(dp);
                    float s0 = __shfl_sync(0xffffffffu, b0, srcA);
                    float s1 = __shfl_sync(0xffffffffu, b1, srcA);
                    float t0s = __shfl_sync(0xffffffffu, b0, srcB);
                    float t1s = __shfl_sync(0xffffffffu, b1, srcB);
                    b0 = fmaf(iZ, s1, Z * s0);
                    b1 = fmaf(c11, t1s, c10 * t0s);
                }
            }
        }

        // ---- main (stores, no predicate) ----
#pragma unroll 2
        for (int g = CH - 4; g >= 0; g -= 4) {
            float lr = -lg2(warp_max_pos(b0 + b1));
            const int tv = (tb + g) >> 1;
            float4 cA = __ldg(ch4 + tv);
            float4 cB = __ldg(ch4 + tv + 1);
            float4 dd = __ldg(la4 + ((tb + g) >> 2));
            float l0v[4] = {cA.x, cA.z, cB.x, cB.z};
            float l1v[4] = {cA.y, cA.w, cB.y, cB.w};
            float lav[4] = {dd.x, dd.y, dd.z, dd.w};
            unsigned u[4];
#pragma unroll
            for (int kk = 0; kk < 4; kk++) {
                int k = 3 - kk;
                u[k] = pack16(b0, b1);   // carry = beta_{t+1} at slot t = g + k

                float a = x0L * l0v[k];
                float b2 = fmaf(x1L, l1v[k], xbL * lav[k]);
                float sm = a + b2, df = a - b2;
                float zp, zm, dp, dn;
                if (kk == 0) { zp = sm + lr; zm = lr - sm; dp = lr + df; dn = lr - df; }
                else         { zp = sm;      zm = -sm;      dp = df;      dn = -df;     }
                float Z   = ex2(zp);
                float iZ  = ex2(zm);
                float c10 = ex2(dn);
                float c11 = ex2(dp);
                float s0 = __shfl_sync(0xffffffffu, b0, srcA);
                float s1 = __shfl_sync(0xffffffffu, b1, srcA);
                float t0s = __shfl_sync(0xffffffffu, b0, srcB);
                float t1s = __shfl_sync(0xffffffffu, b1, srcB);
                b0 = fmaf(iZ, s1, Z * s0);
                b1 = fmaf(c11, t1s, c10 * t0s);
            }
            *reinterpret_cast<uint4*>(&sB[L][g]) = make_uint4(u[0], u[1], u[2], u[3]);
        }
    }

    __syncthreads();

    // ---- LLR: lane-per-t, sign-group partial sums ----
    {
        int tl = w * 32 + L;
        int t = tb + tl;
        float2 l01 = __ldg((const float2*)ch + t);
        float l0 = l01.x, l1 = l01.y;
        float laa = __ldg(la + t);

        float sp = 0.5f * LOG2E * (l0 + l1);
        float dm = 0.5f * LOG2E * (l0 - l1);
        float P   = ex2(sp);
        float iPv = ex2(-sp);
        float Q   = ex2(dm);
        float iQv = ex2(-dm);

        float T0[4] = {0, 0, 0, 0};
        float T1[4] = {0, 0, 0, 0};
        float U0[4] = {0, 0, 0, 0};
        float U1[4] = {0, 0, 0, 0};
#pragma unroll
        for (int s = 0; s < 32; s++) {
            const int par0 = (__popc(s & 28)) & 1;
            const int par1 = (__popc(s & 13)) & 1;
            const int gI = par0 * 2 + par1;

            float2 a  = unpack16(sA[s][tl]);
            float2 bb = unpack16(sB[s][tl]);
            T0[gI] = fmaf(bb.x, a.x, T0[gI]);
            T1[gI] = fmaf(bb.x, a.y, T1[gI]);
            U0[gI] = fmaf(bb.y, a.x, U0[gI]);
            U1[gI] = fmaf(bb.y, a.y, U1[gI]);
        }
        // group: 0 -> X=P, 1 -> X=Q, 2 -> X=iQ, 3 -> X=iP
        float S0 = P   * (T0[0] + T1[3]) + iPv * (T1[0] + T0[3])
                 + Q   * (T0[1] + T1[2]) + iQv * (T1[1] + T0[2]);
        float S1 = P   * (U1[0] + U0[3]) + iPv * (U0[0] + U1[3])
                 + Q   * (U1[1] + U0[2]) + iQv * (U0[1] + U1[2]);

        out[(size_t)b * TT + t] = fmaf(LN2, lg2(S0) - lg2(S1), laa);
    }
}

extern "C" void kernel_launch(void* const* d_in, const int* in_sizes, int n_in,
                              void* d_out, int out_size) {
    const float* llr_ch = (const float*)d_in[0];   // [256, 4096]
    const float* llr_a  = (const float*)d_in[1];   // [256, 2048]
    float* out = (float*)d_out;                    // [256, 2048]

    bcjr_kernel<<<BB * NCHUNK, 64>>>(llr_ch, llr_a, out);
}